// round 4
// baseline (speedup 1.0000x reference)
#include <cuda_runtime.h>
#include <math.h>

// ---------------------------------------------------------------------------
// Problem constants
// ---------------------------------------------------------------------------
namespace {
constexpr int T_  = 4;
constexpr int N_  = 512;
constexpr int C_  = 8;
constexpr int D_  = 128;
constexpr int DM_ = 128;
constexpr int K_  = 16;
constexpr int M_  = N_ * C_;     // 4096 points per t
constexpr int RP  = T_ * M_;     // 16384 point-rows
constexpr int RN  = RP * K_;     // 262144 neighbor-rows
}

// ---------------------------------------------------------------------------
// Scratch (device globals; no allocation allowed). Zero-initialized at load.
// ---------------------------------------------------------------------------
__device__ float g_zero[128];          // permanent zero bias
__device__ float g_x  [RP * DM_];
__device__ float g_q  [RP * DM_];
__device__ float g_k  [RP * DM_];
__device__ float g_v  [RP * DM_];
__device__ float g_res[RP * DM_];
__device__ int   g_knn[RP * K_];
__device__ float g_pos[RN * DM_];

// ---------------------------------------------------------------------------
// Packed fp32x2 helpers (Blackwell FFMA2 path; ptxas never emits it from C++)
// ---------------------------------------------------------------------------
__device__ __forceinline__ unsigned long long pack2(float lo, float hi) {
    unsigned long long r;
    asm("mov.b64 %0, {%1, %2};" : "=l"(r) : "f"(lo), "f"(hi));
    return r;
}
__device__ __forceinline__ void unpack2(unsigned long long v, float& lo, float& hi) {
    asm("mov.b64 {%0, %1}, %2;" : "=f"(lo), "=f"(hi) : "l"(v));
}
__device__ __forceinline__ void fma2(unsigned long long& acc,
                                     unsigned long long a,
                                     unsigned long long b) {
    asm("fma.rn.f32x2 %0, %1, %2, %0;" : "+l"(acc) : "l"(a), "l"(b));
}

__device__ __forceinline__ void store_dup4(float2* sA, int i, float4 v) {
    // sA[i..i+3] = {v.x,v.x},{v.y,v.y},{v.z,v.z},{v.w,v.w}; i % 4 == 0
    *(float4*)&sA[i + 0] = make_float4(v.x, v.x, v.y, v.y);
    *(float4*)&sA[i + 2] = make_float4(v.z, v.z, v.w, v.w);
}

// ---------------------------------------------------------------------------
// Generic fp32 GEMM:  C[rows x 128] = act(Asrc[rows x 128] @ B[128 x 128] + bias)
// Block: 256 threads, tile 64 rows x 128 cols.
// smem: B [128][128] (64KB) + A duplicated {a,a} pairs (64KB) -> 1 CTA/SM.
// A-tile sources:
//   PLAIN: global A
//   POSH : relu((xyz[m]-xyz[knn]) @ w1 + b1)  computed on the fly
// ---------------------------------------------------------------------------
struct GP {
    const float* A; const float* B; const float* bias; float* C;
    const float* xyz; const int* knn; const float* w1; const float* b1;
};

enum { ASRC_PLAIN = 0, ASRC_POSH = 1 };

template <int ASRC>
__global__ void __launch_bounds__(256, 1) gemm128_kernel(GP p)
{
    extern __shared__ float sm[];
    float*  sB = sm;                          // [128][128]
    float2* sA = (float2*)(sm + 128 * 128);   // [64][128] duplicated pairs
    __shared__ float srel[64 * 3];

    const int tid = threadIdx.x;
    const long bm = (long)blockIdx.x * 64;

    for (int i = tid * 4; i < 128 * 128; i += 1024)
        *(float4*)&sB[i] = *(const float4*)&p.B[i];

    if (ASRC == ASRC_POSH) {
        if (tid < 64) {
            long gr = bm + tid;
            int idx = p.knn[gr];
            int tm  = (int)(gr >> 4);
            int t   = tm >> 12;          // / 4096
            int m   = tm & 4095;
            const float* xz = p.xyz + (long)t * M_ * 3;
            srel[tid * 3 + 0] = xz[m * 3 + 0] - xz[idx * 3 + 0];
            srel[tid * 3 + 1] = xz[m * 3 + 1] - xz[idx * 3 + 1];
            srel[tid * 3 + 2] = xz[m * 3 + 2] - xz[idx * 3 + 2];
        }
        __syncthreads();
        for (int i = tid * 4; i < 64 * 128; i += 1024) {
            int row = i >> 7, col = i & 127;
            float rx = srel[row * 3 + 0];
            float ry = srel[row * 3 + 1];
            float rz = srel[row * 3 + 2];
            float4 wa = *(const float4*)&p.w1[col];
            float4 wb = *(const float4*)&p.w1[128 + col];
            float4 wc = *(const float4*)&p.w1[256 + col];
            float4 bb = *(const float4*)&p.b1[col];
            float4 o;
            o.x = fmaxf(fmaf(rx, wa.x, fmaf(ry, wb.x, fmaf(rz, wc.x, bb.x))), 0.f);
            o.y = fmaxf(fmaf(rx, wa.y, fmaf(ry, wb.y, fmaf(rz, wc.y, bb.y))), 0.f);
            o.z = fmaxf(fmaf(rx, wa.z, fmaf(ry, wb.z, fmaf(rz, wc.z, bb.z))), 0.f);
            o.w = fmaxf(fmaf(rx, wa.w, fmaf(ry, wb.w, fmaf(rz, wc.w, bb.w))), 0.f);
            store_dup4(sA, i, o);
        }
    } else {
        for (int i = tid * 4; i < 64 * 128; i += 1024) {
            float4 v = *(const float4*)&p.A[bm * 128 + i];
            store_dup4(sA, i, v);
        }
    }
    __syncthreads();

    const int cg = tid & 31;    // cols cg*4 .. cg*4+3
    const int rg = tid >> 5;    // rows rg*8 .. rg*8+7  (warp id)
    unsigned long long acc[8][2];
#pragma unroll
    for (int j = 0; j < 8; ++j) { acc[j][0] = 0ull; acc[j][1] = 0ull; }

    const float2* sArow = sA + rg * 8 * 128;   // this warp's 8 rows

#pragma unroll 8
    for (int d = 0; d < 128; ++d) {
        float4 b = *(float4*)&sB[d * 128 + cg * 4];
        unsigned long long bxy = pack2(b.x, b.y);
        unsigned long long bzw = pack2(b.z, b.w);
#pragma unroll
        for (int j = 0; j < 8; ++j) {
            unsigned long long aa =
                *(const unsigned long long*)&sArow[j * 128 + d];  // {a,a} broadcast
            fma2(acc[j][0], aa, bxy);
            fma2(acc[j][1], aa, bzw);
        }
    }

    float4 bb = *(const float4*)&p.bias[cg * 4];
#pragma unroll
    for (int j = 0; j < 8; ++j) {
        float4 o;
        unpack2(acc[j][0], o.x, o.y);
        unpack2(acc[j][1], o.z, o.w);
        o.x += bb.x; o.y += bb.y; o.z += bb.z; o.w += bb.w;
        *(float4*)&p.C[(bm + rg * 8 + j) * 128 + cg * 4] = o;
    }
}

// ---------------------------------------------------------------------------
// Fused gamma-MLP + softmax + aggregate. One CTA = 64 neighbor-rows
// = 4 points x 16 neighbors (tile never crosses a t boundary).
//
//   a0   = q[tm] - k[knn] + pos              (built into smem, duplicated)
//   h    = relu(a0 @ gw1 + gb1)              (mainloop 1, FFMA2, kept in smem)
//   a    = (h @ gw2 + gb2) * 1/sqrt(DM)      (mainloop 2, d-pair FFMA2)
//   res  = sum_k softmax_k(a) * relu(v[knn] + pos)
//
// smem (dynamic, floats):
//   [    0,16384) sB1: gw1, [d][c] row-major
//   [16384,32768) sB2: gw2 pair-packed: sB2[(d/2)*256 + c*2 + (d&1)]
//   [32768,49152) sW : phase 1 a0-dup (16384) -> phase 2 h [64][128] (8192)
//                      -> phase 3 a [64][128] at offset 8192
//   [49152,57344) sPos: pos tile [64][128]
// Total 224KB -> 1 CTA/SM.
// ---------------------------------------------------------------------------
struct GF {
    const float* q; const float* k; const float* v; const float* pos;
    const int* knn;
    const float* B1; const float* b1; const float* B2; const float* b2;
    float* res;
};

__global__ void __launch_bounds__(256, 1) gamma_soft_kernel(GF p)
{
    extern __shared__ float sm[];
    float* sB1  = sm;                 // 16384 floats
    float* sB2  = sm + 16384;         // 16384 floats (pair-packed)
    float* sW   = sm + 32768;         // 16384 floats (phased)
    float* sPos = sm + 49152;         // 8192 floats
    __shared__ int sidx[64];

    const int tid = threadIdx.x;
    const long bm = (long)blockIdx.x * 64;   // neighbor-row base
    const int tp0 = blockIdx.x * 4;          // first point (tm) in tile
    const int t   = tp0 >> 12;

    // ---- loads ----
    for (int i = tid * 4; i < 16384; i += 1024)
        *(float4*)&sB1[i] = *(const float4*)&p.B1[i];
    for (int i = tid * 4; i < 16384; i += 1024) {
        float4 w = *(const float4*)&p.B2[i];
        int d = i >> 7, c = i & 127;
        int base = (d >> 1) * 256 + (d & 1);
        sB2[base + (c + 0) * 2] = w.x;
        sB2[base + (c + 1) * 2] = w.y;
        sB2[base + (c + 2) * 2] = w.z;
        sB2[base + (c + 3) * 2] = w.w;
    }
    if (tid < 64) sidx[tid] = p.knn[bm + tid];
    for (int i = tid * 4; i < 8192; i += 1024)
        *(float4*)&sPos[i] = *(const float4*)&p.pos[bm * 128 + i];
    __syncthreads();

    // ---- build a0 tile (duplicated {a,a} pairs) ----
    float2* sA = (float2*)sW;
    for (int i = tid * 4; i < 8192; i += 1024) {
        int row = i >> 7, col = i & 127;
        int tm  = (int)((bm + row) >> 4);
        float4 qv = *(const float4*)&p.q[(long)tm * 128 + col];
        float4 kv = *(const float4*)&p.k[(((long)t << 12) + sidx[row]) * 128 + col];
        float4 pv = *(float4*)&sPos[i];
        float4 o;
        o.x = qv.x - kv.x + pv.x;
        o.y = qv.y - kv.y + pv.y;
        o.z = qv.z - kv.z + pv.z;
        o.w = qv.w - kv.w + pv.w;
        store_dup4(sA, i, o);
    }
    __syncthreads();

    const int cg = tid & 31;
    const int rg = tid >> 5;

    // ---- mainloop 1: h = relu(a0 @ B1 + b1) ----
    unsigned long long acc1[8][2];
#pragma unroll
    for (int j = 0; j < 8; ++j) { acc1[j][0] = 0ull; acc1[j][1] = 0ull; }
    {
        const float2* sArow = sA + rg * 8 * 128;
#pragma unroll 8
        for (int d = 0; d < 128; ++d) {
            float4 b = *(float4*)&sB1[d * 128 + cg * 4];
            unsigned long long bxy = pack2(b.x, b.y);
            unsigned long long bzw = pack2(b.z, b.w);
#pragma unroll
            for (int j = 0; j < 8; ++j) {
                unsigned long long aa =
                    *(const unsigned long long*)&sArow[j * 128 + d];
                fma2(acc1[j][0], aa, bxy);
                fma2(acc1[j][1], aa, bzw);
            }
        }
    }
    __syncthreads();   // all warps done reading sA before h overwrite

    float* sH = sW;    // [64][128]
    {
        float4 b1v = *(const float4*)&p.b1[cg * 4];
#pragma unroll
        for (int j = 0; j < 8; ++j) {
            float4 o;
            unpack2(acc1[j][0], o.x, o.y);
            unpack2(acc1[j][1], o.z, o.w);
            o.x = fmaxf(o.x + b1v.x, 0.f);
            o.y = fmaxf(o.y + b1v.y, 0.f);
            o.z = fmaxf(o.z + b1v.z, 0.f);
            o.w = fmaxf(o.w + b1v.w, 0.f);
            *(float4*)&sH[(rg * 8 + j) * 128 + cg * 4] = o;
        }
    }
    __syncthreads();

    // ---- mainloop 2: a = (h @ B2 + b2) * scale, d-pair packed ----
    unsigned long long acc2[8][4];
#pragma unroll
    for (int j = 0; j < 8; ++j)
#pragma unroll
        for (int c = 0; c < 4; ++c) acc2[j][c] = 0ull;
    {
        const float* sHrow = sH + rg * 8 * 128;
#pragma unroll 4
        for (int dp = 0; dp < 64; ++dp) {
            const unsigned long long* pb =
                (const unsigned long long*)&sB2[dp * 256 + cg * 8];
            unsigned long long b0 = pb[0];   // pair for col cg*4+0
            unsigned long long b1p = pb[1];  // col cg*4+1
            unsigned long long b2p = pb[2];  // col cg*4+2
            unsigned long long b3p = pb[3];  // col cg*4+3
#pragma unroll
            for (int j = 0; j < 8; ++j) {
                unsigned long long aa =
                    *(const unsigned long long*)&sHrow[j * 128 + 2 * dp];
                fma2(acc2[j][0], aa, b0);
                fma2(acc2[j][1], aa, b1p);
                fma2(acc2[j][2], aa, b2p);
                fma2(acc2[j][3], aa, b3p);
            }
        }
    }

    float* sAa = sW + 8192;   // [64][128] a tile (disjoint from sH)
    {
        const float scale = 0.08838834764831845f;  // 1/sqrt(128)
        float4 b2v = *(const float4*)&p.b2[cg * 4];
        float bias[4] = {b2v.x, b2v.y, b2v.z, b2v.w};
#pragma unroll
        for (int j = 0; j < 8; ++j) {
            float4 o;
            float lo, hi;
            unpack2(acc2[j][0], lo, hi); o.x = (lo + hi + bias[0]) * scale;
            unpack2(acc2[j][1], lo, hi); o.y = (lo + hi + bias[1]) * scale;
            unpack2(acc2[j][2], lo, hi); o.z = (lo + hi + bias[2]) * scale;
            unpack2(acc2[j][3], lo, hi); o.w = (lo + hi + bias[3]) * scale;
            *(float4*)&sAa[(rg * 8 + j) * 128 + cg * 4] = o;
        }
    }
    __syncthreads();

    // ---- softmax over K + aggregate relu(v_gather + pos) ----
#pragma unroll
    for (int rep = 0; rep < 2; ++rep) {
        const int pp = (tid >> 7) + rep * 2;   // point within tile, 0..3
        const int c  = tid & 127;              // channel
        const int r0 = pp * 16;

        float av[K_];
        float mx = -INFINITY;
#pragma unroll
        for (int kk = 0; kk < K_; ++kk) {
            av[kk] = sAa[(r0 + kk) * 128 + c];
            mx = fmaxf(mx, av[kk]);
        }
        float s = 0.f;
#pragma unroll
        for (int kk = 0; kk < K_; ++kk) {
            av[kk] = __expf(av[kk] - mx);
            s += av[kk];
        }
        const float inv = 1.f / s;

        float r = 0.f;
#pragma unroll
        for (int kk = 0; kk < K_; ++kk) {
            int idx = sidx[r0 + kk];
            float vv = p.v[(((long)t << 12) + idx) * 128 + c]
                     + sPos[(r0 + kk) * 128 + c];
            r = fmaf(av[kk], fmaxf(vv, 0.f), r);
        }
        p.res[(long)(tp0 + pp) * 128 + c] = r * inv;
    }
}

// ---------------------------------------------------------------------------
// x = feats @ fc1_w + fc1_b with feats[t,m,d] = features[t,d,m] (on-the-fly
// transpose). Block tile: 64 m-rows x 128 cols, per t. (~1% of total work.)
// ---------------------------------------------------------------------------
__global__ void xproj_kernel(const float* __restrict__ features,
                             const float* __restrict__ W,
                             const float* __restrict__ bias,
                             float* __restrict__ X)
{
    extern __shared__ float sm[];
    float* sAT = sm;                 // [128 d][64 ml]  (transposed tile)
    float* sB  = sm + 128 * 64;      // [128][128]

    const int tid = threadIdx.x;
    const int t   = blockIdx.y;
    const int bm  = blockIdx.x * 64;

    for (int i = tid * 4; i < 128 * 128; i += 1024)
        *(float4*)&sB[i] = *(const float4*)&W[i];
    for (int i = tid; i < 128 * 64; i += 256) {
        int d  = i >> 6;
        int ml = i & 63;
        sAT[d * 64 + ml] = features[((long)t * D_ + d) * M_ + bm + ml];
    }
    __syncthreads();

    const int cg = tid & 31;
    const int rg = tid >> 5;
    float acc[8][4];
#pragma unroll
    for (int j = 0; j < 8; ++j)
#pragma unroll
        for (int c = 0; c < 4; ++c) acc[j][c] = 0.f;

#pragma unroll 8
    for (int d = 0; d < 128; ++d) {
        float4 b = *(float4*)&sB[d * 128 + cg * 4];
#pragma unroll
        for (int j = 0; j < 8; ++j) {
            float a = sAT[d * 64 + rg * 8 + j];   // warp-broadcast
            acc[j][0] = fmaf(a, b.x, acc[j][0]);
            acc[j][1] = fmaf(a, b.y, acc[j][1]);
            acc[j][2] = fmaf(a, b.z, acc[j][2]);
            acc[j][3] = fmaf(a, b.w, acc[j][3]);
        }
    }

    float4 bb = *(const float4*)&bias[cg * 4];
#pragma unroll
    for (int j = 0; j < 8; ++j) {
        float4 o;
        o.x = acc[j][0] + bb.x;
        o.y = acc[j][1] + bb.y;
        o.z = acc[j][2] + bb.z;
        o.w = acc[j][3] + bb.w;
        *(float4*)&X[((long)t * M_ + bm + rg * 8 + j) * 128 + cg * 4] = o;
    }
}

// ---------------------------------------------------------------------------
// KNN: block per query point (t,m); 128 threads. Select 17 smallest with
// stable tie-break by index, drop rank 0 (self). Downstream use (softmax over
// K then sum over K) is permutation-invariant, so any order matching the
// stable-sort SET of argsort[...,1:K+1] is exact.
// ---------------------------------------------------------------------------
__global__ void knn_kernel(const float* __restrict__ xyz,
                           const float* __restrict__ mask,
                           int* __restrict__ knn)
{
    __shared__ float sd[M_];          // 16KB
    __shared__ float rv[128];
    __shared__ int   ri[128];

    const int t = blockIdx.x >> 12;
    const int m = blockIdx.x & 4095;
    const int tid = threadIdx.x;

    const float* xz = xyz + (long)t * M_ * 3;
    const float x0 = xz[m * 3 + 0];
    const float y0 = xz[m * 3 + 1];
    const float z0 = xz[m * 3 + 2];
    const float mm = mask[(long)t * M_ + m];

    for (int j = tid; j < M_; j += 128) {
        float dx = x0 - xz[j * 3 + 0];
        float dy = y0 - xz[j * 3 + 1];
        float dz = z0 - xz[j * 3 + 2];
        sd[j] = dx * dx + dy * dy + dz * dz
              + (1.0f - mm * mask[(long)t * M_ + j]) * 1e6f;
    }
    __syncthreads();

    for (int r = 0; r < K_ + 1; ++r) {
        float bv = INFINITY;
        int   bi = M_;
        for (int j = tid; j < M_; j += 128) {
            float d = sd[j];
            if (d < bv || (d == bv && j < bi)) { bv = d; bi = j; }
        }
        rv[tid] = bv; ri[tid] = bi;
        __syncthreads();
        for (int s = 64; s > 0; s >>= 1) {
            if (tid < s) {
                if (rv[tid + s] < rv[tid] ||
                    (rv[tid + s] == rv[tid] && ri[tid + s] < ri[tid])) {
                    rv[tid] = rv[tid + s]; ri[tid] = ri[tid + s];
                }
            }
            __syncthreads();
        }
        int win = ri[0];
        if (tid == 0) {
            if (r > 0) knn[(long)blockIdx.x * K_ + (r - 1)] = win;
            sd[win] = INFINITY;
        }
        __syncthreads();
    }
}

// ---------------------------------------------------------------------------
// out[t,d,m] = cfc2[t,m,d] + features[t,d,m]   (transpose + residual)
// ---------------------------------------------------------------------------
__global__ void out_kernel(const float* __restrict__ cfc2,
                           const float* __restrict__ features,
                           float* __restrict__ out)
{
    const long i = (long)blockIdx.x * blockDim.x + threadIdx.x;
    if (i >= (long)T_ * D_ * M_) return;
    const int  m  = (int)(i & 4095);
    const long td = i >> 12;
    const int  d  = (int)(td & 127);
    const int  t  = (int)(td >> 7);
    out[i] = cfc2[((long)t * M_ + m) * 128 + d] + features[i];
}

// ---------------------------------------------------------------------------
// Launch
// ---------------------------------------------------------------------------
extern "C" void kernel_launch(void* const* d_in, const int* in_sizes, int n_in,
                              void* d_out, int out_size)
{
    const float* features = (const float*)d_in[0];
    const float* xyz      = (const float*)d_in[1];
    const float* mask     = (const float*)d_in[2];
    const float* fc1_w    = (const float*)d_in[3];
    const float* fc1_b    = (const float*)d_in[4];
    const float* fc2_w    = (const float*)d_in[5];
    const float* fc2_b    = (const float*)d_in[6];
    const float* dw1      = (const float*)d_in[7];
    const float* db1      = (const float*)d_in[8];
    const float* dw2      = (const float*)d_in[9];
    const float* db2      = (const float*)d_in[10];
    const float* gw1      = (const float*)d_in[11];
    const float* gb1      = (const float*)d_in[12];
    const float* gw2      = (const float*)d_in[13];
    const float* gb2      = (const float*)d_in[14];
    const float* wq       = (const float*)d_in[15];
    const float* wk       = (const float*)d_in[16];
    const float* wv       = (const float*)d_in[17];
    float* out = (float*)d_out;

    const int GEMM_SMEM  = 128 * 128 * 4 + 64 * 128 * 8;   // 128KB
    const int FUSED_SMEM = 57344 * 4;                      // 224KB
    const int XPROJ_SMEM = (128 * 64 + 128 * 128) * 4;     // 96KB

    cudaFuncSetAttribute((const void*)gemm128_kernel<ASRC_PLAIN>,
                         cudaFuncAttributeMaxDynamicSharedMemorySize, GEMM_SMEM);
    cudaFuncSetAttribute((const void*)gemm128_kernel<ASRC_POSH>,
                         cudaFuncAttributeMaxDynamicSharedMemorySize, GEMM_SMEM);
    cudaFuncSetAttribute((const void*)gamma_soft_kernel,
                         cudaFuncAttributeMaxDynamicSharedMemorySize, FUSED_SMEM);
    cudaFuncSetAttribute((const void*)xproj_kernel,
                         cudaFuncAttributeMaxDynamicSharedMemorySize, XPROJ_SMEM);

    float *x, *q, *k, *v, *res, *pos, *zero;
    int* knn;
    cudaGetSymbolAddress((void**)&x,    g_x);
    cudaGetSymbolAddress((void**)&q,    g_q);
    cudaGetSymbolAddress((void**)&k,    g_k);
    cudaGetSymbolAddress((void**)&v,    g_v);
    cudaGetSymbolAddress((void**)&res,  g_res);
    cudaGetSymbolAddress((void**)&knn,  g_knn);
    cudaGetSymbolAddress((void**)&pos,  g_pos);
    cudaGetSymbolAddress((void**)&zero, g_zero);
    float* fc2o = x;   // x is dead after q/k/v projections

    // 1) x = feats @ fc1_w + fc1_b (fused transpose of features)
    {
        dim3 grid(M_ / 64, T_);
        xproj_kernel<<<grid, 256, XPROJ_SMEM>>>(features, fc1_w, fc1_b, x);
    }

    // 2) KNN
    knn_kernel<<<RP, 128>>>(xyz, mask, knn);

    // 3) q, k, v (no bias in reference -> g_zero)
    {
        GP p{}; p.B = wq; p.bias = zero; p.A = x; p.C = q;
        gemm128_kernel<ASRC_PLAIN><<<RP / 64, 256, GEMM_SMEM>>>(p);
        p.B = wk; p.C = k;
        gemm128_kernel<ASRC_PLAIN><<<RP / 64, 256, GEMM_SMEM>>>(p);
        p.B = wv; p.C = v;
        gemm128_kernel<ASRC_PLAIN><<<RP / 64, 256, GEMM_SMEM>>>(p);
    }

    // 4) pos = relu(rel @ dw1 + db1) @ dw2 + db2   (ph fused into A-load)
    {
        GP p{}; p.B = dw2; p.bias = db2; p.C = pos;
        p.xyz = xyz; p.knn = knn; p.w1 = dw1; p.b1 = db1;
        gemm128_kernel<ASRC_POSH><<<RN / 64, 256, GEMM_SMEM>>>(p);
    }

    // 5) fused: h -> a -> softmax -> aggregate  (g_h / g_a never hit HBM)
    {
        GF p{};
        p.q = q; p.k = k; p.v = v; p.pos = pos; p.knn = knn;
        p.B1 = gw1; p.b1 = gb1; p.B2 = gw2; p.b2 = gb2;
        p.res = res;
        gamma_soft_kernel<<<RN / 64, 256, FUSED_SMEM>>>(p);
    }

    // 6) fc2 + residual + transpose back to [t,d,n,c]
    {
        GP p{}; p.A = res; p.B = fc2_w; p.bias = fc2_b; p.C = fc2o;
        gemm128_kernel<ASRC_PLAIN><<<RP / 64, 256, GEMM_SMEM>>>(p);
    }
    {
        long total = (long)T_ * D_ * M_;
        int blocks = (int)((total + 255) / 256);
        out_kernel<<<blocks, 256>>>(fc2o, features, out);
    }
    (void)in_sizes; (void)n_in; (void)out_size;
}

// round 11
// speedup vs baseline: 2.0311x; 2.0311x over previous
#include <cuda_runtime.h>
#include <cuda_bf16.h>
#include <math.h>
#include <stdint.h>

// ---------------------------------------------------------------------------
// Problem constants
// ---------------------------------------------------------------------------
namespace {
constexpr int T_  = 4;
constexpr int N_  = 512;
constexpr int C_  = 8;
constexpr int D_  = 128;
constexpr int DM_ = 128;
constexpr int K_  = 16;
constexpr int M_  = N_ * C_;     // 4096
constexpr int RP  = T_ * M_;     // 16384
constexpr int RN  = RP * K_;     // 262144

constexpr int PK    = 136;             // padded bf16 row stride (272 B)
constexpr int TILEB = 128 * PK * 2;    // 34816 bytes per 128x128 bf16 tile
constexpr int PAW   = 132;             // padded fp32 stride for the 'a' tile
}

extern __shared__ __align__(1024) char dsm[];

// ---------------------------------------------------------------------------
// Scratch (device globals; zero-initialized; no allocation allowed)
// ---------------------------------------------------------------------------
__device__ float          g_zero[128];
__device__ __nv_bfloat16  g_xbf [RP * DM_];
__device__ float          g_q   [RP * DM_];
__device__ float          g_k   [RP * DM_];
__device__ float          g_v   [RP * DM_];
__device__ float          g_pos [RN * DM_];
__device__ __nv_bfloat16  g_resb[RP * DM_];
__device__ int            g_knn [RP * K_];
__device__ __nv_bfloat16  g_wimg[7 * 16384];   // bf16 W^T images, [n][k] row-major

// ---------------------------------------------------------------------------
// Warp-level bf16 MMA (baseline PTX, supported on plain sm_103 target)
// ---------------------------------------------------------------------------
__device__ __forceinline__ void mma16816(float* c, const uint32_t* a,
                                         uint32_t b0, uint32_t b1) {
    asm volatile(
        "mma.sync.aligned.m16n8k16.row.col.f32.bf16.bf16.f32 "
        "{%0,%1,%2,%3}, {%4,%5,%6,%7}, {%8,%9}, {%0,%1,%2,%3};"
        : "+f"(c[0]), "+f"(c[1]), "+f"(c[2]), "+f"(c[3])
        : "r"(a[0]), "r"(a[1]), "r"(a[2]), "r"(a[3]), "r"(b0), "r"(b1));
}

// Warp computes a 32x64 slice of C = A[128xK=128] @ B^T (B stored [n][k]).
// Fragment mapping per PTX ISA (m16n8k16, .row.col):
//   A: a0a1=(r,qc), a2a3=(r+8,qc), a4a5=(r,qc+8), a6a7=(r+8,qc+8)
//   B: b0=(k=qc..qc+1, n), b1=(k=qc+8.., n)  with n = ntile*8 + lane/4
// Padded stride PK=136 (272B): bank = (row*68 + word) & 31 -> conflict-free.
__device__ __forceinline__ void warp_mma_tile(
    const __nv_bfloat16* sA, const __nv_bfloat16* sB,
    int wm, int wn, int lane, float acc[2][8][4])
{
    const int rq = lane >> 2;
    const int qc = (lane & 3) * 2;
#pragma unroll
    for (int ks = 0; ks < 8; ++ks) {
        const int k0 = ks * 16;
        uint32_t a[2][4];
#pragma unroll
        for (int mt = 0; mt < 2; ++mt) {
            const __nv_bfloat16* ar = sA + (wm * 32 + mt * 16 + rq) * PK + k0 + qc;
            a[mt][0] = *(const uint32_t*)(ar);
            a[mt][1] = *(const uint32_t*)(ar + 8 * PK);
            a[mt][2] = *(const uint32_t*)(ar + 8);
            a[mt][3] = *(const uint32_t*)(ar + 8 * PK + 8);
        }
#pragma unroll
        for (int nt = 0; nt < 8; ++nt) {
            const __nv_bfloat16* br = sB + (wn * 64 + nt * 8 + rq) * PK + k0 + qc;
            uint32_t b0 = *(const uint32_t*)(br);
            uint32_t b1 = *(const uint32_t*)(br + 8);
            mma16816(acc[0][nt], a[0], b0, b1);
            mma16816(acc[1][nt], a[1], b0, b1);
        }
    }
}

// ---------------------------------------------------------------------------
// Weight prep: img[b][n][k] = bf16(W_b[k][n])   (W^T, row-major [n][k])
// ---------------------------------------------------------------------------
struct WP { const float* w[7]; };
__global__ void prep_weights(WP p, __nv_bfloat16* img)
{
    const int b = blockIdx.x;
    const float* W = p.w[b];
    __nv_bfloat16* base = img + b * 16384;
    for (int i = threadIdx.x; i < 16384; i += blockDim.x) {
        int n = i >> 7, k = i & 127;
        base[i] = __float2bfloat16(W[k * 128 + n]);
    }
}

// ---------------------------------------------------------------------------
// Tensor-core GEMM: C[128-row tile][128] = A @ W + bias (fp32 out).
// 256 threads (8 warps, 4x2). smem: hdr 2048 | A 34816 | B 34816 = 71680
// -> 2 CTA/SM.
// ASRC_PLAIN: A from linear bf16 gmem. ASRC_POSH: A = relu(rel@w1+b1).
// ---------------------------------------------------------------------------
enum { ASRC_PLAIN = 0, ASRC_POSH = 1 };
struct MG {
    const __nv_bfloat16* Abf; const __nv_bfloat16* Bimg;
    const float* bias; float* C;
    const float* xyz; const int* knn; const float* w1; const float* b1;
};

template <int ASRC>
__global__ void __launch_bounds__(256, 2) mma_gemm(MG p)
{
    char* smem = dsm;
    float* sbias = (float*)smem;                       // 512 B
    float* srel  = (float*)(smem + 512);               // 1536 B (POSH)
    __nv_bfloat16* sA = (__nv_bfloat16*)(smem + 2048);
    __nv_bfloat16* sB = (__nv_bfloat16*)(smem + 2048 + TILEB);

    const int tid = threadIdx.x;
    const long bm = (long)blockIdx.x * 128;

    if (tid < 128) sbias[tid] = p.bias[tid];

    // B image [n][k] -> padded smem
    for (int i = tid * 8; i < 128 * 128; i += 256 * 8) {
        int n = i >> 7, c8 = i & 127;
        *(uint4*)&sB[n * PK + c8] = *(const uint4*)&p.Bimg[i];
    }

    if (ASRC == ASRC_POSH) {
        if (tid < 128) {
            long gr = bm + tid;
            int idx = p.knn[gr];
            int tm  = (int)(gr >> 4);
            int t   = tm >> 12;
            int m   = tm & 4095;
            const float* xz = p.xyz + (long)t * M_ * 3;
            srel[tid * 3 + 0] = xz[m * 3 + 0] - xz[idx * 3 + 0];
            srel[tid * 3 + 1] = xz[m * 3 + 1] - xz[idx * 3 + 1];
            srel[tid * 3 + 2] = xz[m * 3 + 2] - xz[idx * 3 + 2];
        }
        __syncthreads();
        for (int it = 0; it < 8; ++it) {
            int el  = it * 256 + tid;
            int row = el >> 4;
            int c8  = (el & 15) * 8;
            float rx = srel[row * 3 + 0];
            float ry = srel[row * 3 + 1];
            float rz = srel[row * 3 + 2];
            __nv_bfloat16 buf[8];
#pragma unroll
            for (int j = 0; j < 8; ++j) {
                int c = c8 + j;
                float v = fmaf(rx, p.w1[c], fmaf(ry, p.w1[128 + c],
                            fmaf(rz, p.w1[256 + c], p.b1[c])));
                buf[j] = __float2bfloat16(fmaxf(v, 0.f));
            }
            *(uint4*)&sA[row * PK + c8] = *(uint4*)buf;
        }
    } else {
        for (int it = 0; it < 8; ++it) {
            int el  = it * 256 + tid;
            int row = el >> 4;
            int c8  = (el & 15) * 8;
            *(uint4*)&sA[row * PK + c8] = *(const uint4*)&p.Abf[(bm + row) * 128 + c8];
        }
    }
    __syncthreads();

    const int lane = tid & 31;
    const int wm = tid >> 6;          // 0..3
    const int wn = (tid >> 5) & 1;    // 0..1
    float acc[2][8][4];
#pragma unroll
    for (int mt = 0; mt < 2; ++mt)
#pragma unroll
        for (int nt = 0; nt < 8; ++nt)
#pragma unroll
            for (int c = 0; c < 4; ++c) acc[mt][nt][c] = 0.f;

    warp_mma_tile(sA, sB, wm, wn, lane, acc);

    const int rq = lane >> 2;
    const int qc = (lane & 3) * 2;
#pragma unroll
    for (int mt = 0; mt < 2; ++mt) {
#pragma unroll
        for (int nt = 0; nt < 8; ++nt) {
            int R  = wm * 32 + mt * 16 + rq;
            int Cc = wn * 64 + nt * 8 + qc;
            float bx = sbias[Cc], by = sbias[Cc + 1];
            float2 lo = make_float2(acc[mt][nt][0] + bx, acc[mt][nt][1] + by);
            float2 hi = make_float2(acc[mt][nt][2] + bx, acc[mt][nt][3] + by);
            *(float2*)&p.C[(bm + R) * 128 + Cc]     = lo;
            *(float2*)&p.C[(bm + R + 8) * 128 + Cc] = hi;
        }
    }
}

// ---------------------------------------------------------------------------
// Fused gamma MLP + softmax + aggregate (tensor-core, mma.sync).
// CTA = 128 neighbor-rows = 8 points x 16 neighbors.
//   a0 = q - k[knn] + pos      -> MMA1 (@gw1) -> h = relu(.+gb1) in smem
//   h @ gw2                    -> MMA2 -> a = (.+gb2)*scale in smem (fp32)
//   res = sum_k softmax_k(a) * relu(v[knn]+pos)
// smem: hdr 2048 | B1 | B2 | A | H (34816 each) | posB 32768 = 174080.
// aW fp32 [128][132] overlays A+H after MMA2.
// ---------------------------------------------------------------------------
struct GF {
    const float* q; const float* k; const float* v; const float* pos;
    const int* knn;
    const __nv_bfloat16* B1img; const __nv_bfloat16* B2img;
    const float* b1; const float* b2;
    __nv_bfloat16* res;
};

__global__ void __launch_bounds__(256, 1) gamma_soft_mma(GF p)
{
    char* smem = dsm;
    int*   sidx = (int*)smem;                          // 512 B
    float* sb1v = (float*)(smem + 512);                // 512 B
    float* sb2v = (float*)(smem + 1024);               // 512 B
    __nv_bfloat16* sB1 = (__nv_bfloat16*)(smem + 2048);
    __nv_bfloat16* sB2 = (__nv_bfloat16*)(smem + 2048 + TILEB);
    __nv_bfloat16* sA  = (__nv_bfloat16*)(smem + 2048 + 2 * TILEB);
    __nv_bfloat16* sH  = (__nv_bfloat16*)(smem + 2048 + 3 * TILEB);
    __nv_bfloat16* posB = (__nv_bfloat16*)(smem + 2048 + 4 * TILEB);
    float* aW = (float*)(smem + 2048 + 2 * TILEB);     // overlays A+H (67584 B)

    const int tid = threadIdx.x;
    const long bm = (long)blockIdx.x * 128;    // neighbor-row base
    const int tp0 = blockIdx.x * 8;            // first point
    const int t   = tp0 >> 12;

    if (tid < 128) {
        sidx[tid] = p.knn[bm + tid];
        sb1v[tid] = p.b1[tid];
        sb2v[tid] = p.b2[tid];
    }
    for (int i = tid * 8; i < 128 * 128; i += 256 * 8) {
        int n = i >> 7, c8 = i & 127;
        *(uint4*)&sB1[n * PK + c8] = *(const uint4*)&p.B1img[i];
        *(uint4*)&sB2[n * PK + c8] = *(const uint4*)&p.B2img[i];
    }
    __syncthreads();

    // build a0 (padded bf16) + posB (bf16 linear)
    for (int it = 0; it < 8; ++it) {
        int el  = it * 256 + tid;
        int row = el >> 4;
        int c8  = (el & 15) * 8;
        int tm  = tp0 + (row >> 4);
        const float* qp = &p.q[(long)tm * 128 + c8];
        const float* kp = &p.k[(((long)t << 12) + sidx[row]) * 128 + c8];
        const float* pp = &p.pos[(bm + row) * 128 + c8];
        __nv_bfloat16 abuf[8], pbuf[8];
#pragma unroll
        for (int j = 0; j < 8; ++j) {
            float pv = pp[j];
            abuf[j] = __float2bfloat16(qp[j] - kp[j] + pv);
            pbuf[j] = __float2bfloat16(pv);
        }
        *(uint4*)&sA[row * PK + c8] = *(uint4*)abuf;
        *(uint4*)&posB[row * 128 + c8] = *(uint4*)pbuf;
    }
    __syncthreads();

    const int lane = tid & 31;
    const int wm = tid >> 6;
    const int wn = (tid >> 5) & 1;
    const int rq = lane >> 2;
    const int qc = (lane & 3) * 2;

    // MMA1: a0 @ B1 -> h
    float acc[2][8][4];
#pragma unroll
    for (int mt = 0; mt < 2; ++mt)
#pragma unroll
        for (int nt = 0; nt < 8; ++nt)
#pragma unroll
            for (int c = 0; c < 4; ++c) acc[mt][nt][c] = 0.f;
    warp_mma_tile(sA, sB1, wm, wn, lane, acc);

    // h = relu(acc + b1) -> bf16 padded sH
#pragma unroll
    for (int mt = 0; mt < 2; ++mt) {
#pragma unroll
        for (int nt = 0; nt < 8; ++nt) {
            int R  = wm * 32 + mt * 16 + rq;
            int Cc = wn * 64 + nt * 8 + qc;
            float bx = sb1v[Cc], by = sb1v[Cc + 1];
            __nv_bfloat16 h0[2], h1[2];
            h0[0] = __float2bfloat16(fmaxf(acc[mt][nt][0] + bx, 0.f));
            h0[1] = __float2bfloat16(fmaxf(acc[mt][nt][1] + by, 0.f));
            h1[0] = __float2bfloat16(fmaxf(acc[mt][nt][2] + bx, 0.f));
            h1[1] = __float2bfloat16(fmaxf(acc[mt][nt][3] + by, 0.f));
            *(uint32_t*)&sH[R * PK + Cc]       = *(uint32_t*)h0;
            *(uint32_t*)&sH[(R + 8) * PK + Cc] = *(uint32_t*)h1;
        }
    }
    __syncthreads();

    // MMA2: h @ B2 -> a
#pragma unroll
    for (int mt = 0; mt < 2; ++mt)
#pragma unroll
        for (int nt = 0; nt < 8; ++nt)
#pragma unroll
            for (int c = 0; c < 4; ++c) acc[mt][nt][c] = 0.f;
    warp_mma_tile(sH, sB2, wm, wn, lane, acc);

    __syncthreads();   // all warps done reading sA/sH before aW overlay

    const float scale = 0.08838834764831845f;  // 1/sqrt(128)
#pragma unroll
    for (int mt = 0; mt < 2; ++mt) {
#pragma unroll
        for (int nt = 0; nt < 8; ++nt) {
            int R  = wm * 32 + mt * 16 + rq;
            int Cc = wn * 64 + nt * 8 + qc;
            float bx = sb2v[Cc], by = sb2v[Cc + 1];
            float2 lo = make_float2((acc[mt][nt][0] + bx) * scale,
                                    (acc[mt][nt][1] + by) * scale);
            float2 hi = make_float2((acc[mt][nt][2] + bx) * scale,
                                    (acc[mt][nt][3] + by) * scale);
            *(float2*)&aW[R * PAW + Cc]       = lo;
            *(float2*)&aW[(R + 8) * PAW + Cc] = hi;
        }
    }
    __syncthreads();

    // softmax over K + aggregate relu(v_gather + pos)
    for (int rep = 0; rep < 4; ++rep) {
        const int pp = rep * 2 + (tid >> 7);   // point 0..7
        const int c  = tid & 127;
        const int r0 = pp * 16;

        float av[K_];
        float mx = -INFINITY;
#pragma unroll
        for (int kk = 0; kk < K_; ++kk) {
            av[kk] = aW[(r0 + kk) * PAW + c];
            mx = fmaxf(mx, av[kk]);
        }
        float s = 0.f;
#pragma unroll
        for (int kk = 0; kk < K_; ++kk) {
            av[kk] = __expf(av[kk] - mx);
            s += av[kk];
        }
        const float inv = 1.f / s;

        float r = 0.f;
#pragma unroll
        for (int kk = 0; kk < K_; ++kk) {
            float vv = p.v[(((long)t << 12) + sidx[r0 + kk]) * 128 + c]
                     + __bfloat162float(posB[(r0 + kk) * 128 + c]);
            r = fmaf(av[kk], fmaxf(vv, 0.f), r);
        }
        p.res[(long)(tp0 + pp) * 128 + c] = __float2bfloat16(r * inv);
    }
}

// ---------------------------------------------------------------------------
// x = feats @ fc1_w + fc1_b (transpose of features fused), output bf16.
// ---------------------------------------------------------------------------
__global__ void xproj_kernel(const float* __restrict__ features,
                             const float* __restrict__ W,
                             const float* __restrict__ bias,
                             __nv_bfloat16* __restrict__ X)
{
    float* smf = (float*)dsm;
    float* sAT = smf;                 // [128 d][64 ml]
    float* sB  = smf + 128 * 64;      // [128][128]

    const int tid = threadIdx.x;
    const int t   = blockIdx.y;
    const int bm  = blockIdx.x * 64;

    for (int i = tid * 4; i < 128 * 128; i += 1024)
        *(float4*)&sB[i] = *(const float4*)&W[i];
    for (int i = tid; i < 128 * 64; i += 256) {
        int d  = i >> 6;
        int ml = i & 63;
        sAT[d * 64 + ml] = features[((long)t * D_ + d) * M_ + bm + ml];
    }
    __syncthreads();

    const int cg = tid & 31;
    const int rg = tid >> 5;
    float acc[8][4];
#pragma unroll
    for (int j = 0; j < 8; ++j)
#pragma unroll
        for (int c = 0; c < 4; ++c) acc[j][c] = 0.f;

#pragma unroll 8
    for (int d = 0; d < 128; ++d) {
        float4 b = *(float4*)&sB[d * 128 + cg * 4];
#pragma unroll
        for (int j = 0; j < 8; ++j) {
            float a = sAT[d * 64 + rg * 8 + j];
            acc[j][0] = fmaf(a, b.x, acc[j][0]);
            acc[j][1] = fmaf(a, b.y, acc[j][1]);
            acc[j][2] = fmaf(a, b.z, acc[j][2]);
            acc[j][3] = fmaf(a, b.w, acc[j][3]);
        }
    }

    float4 bb = *(const float4*)&bias[cg * 4];
#pragma unroll
    for (int j = 0; j < 8; ++j) {
        __nv_bfloat16 ob[4];
        ob[0] = __float2bfloat16(acc[j][0] + bb.x);
        ob[1] = __float2bfloat16(acc[j][1] + bb.y);
        ob[2] = __float2bfloat16(acc[j][2] + bb.z);
        ob[3] = __float2bfloat16(acc[j][3] + bb.w);
        *(uint2*)&X[((long)t * M_ + bm + rg * 8 + j) * 128 + cg * 4] = *(uint2*)ob;
    }
}

// ---------------------------------------------------------------------------
// KNN: block per query; 17 smallest (stable tie-break), drop self.
// Order-invariant downstream (softmax+sum over K).
// ---------------------------------------------------------------------------
__global__ void knn_kernel(const float* __restrict__ xyz,
                           const float* __restrict__ mask,
                           int* __restrict__ knn)
{
    __shared__ float sd[M_];
    __shared__ float rv[128];
    __shared__ int   ri[128];

    const int t = blockIdx.x >> 12;
    const int m = blockIdx.x & 4095;
    const int tid = threadIdx.x;

    const float* xz = xyz + (long)t * M_ * 3;
    const float x0 = xz[m * 3 + 0];
    const float y0 = xz[m * 3 + 1];
    const float z0 = xz[m * 3 + 2];
    const float mm = mask[(long)t * M_ + m];

    for (int j = tid; j < M_; j += 128) {
        float dx = x0 - xz[j * 3 + 0];
        float dy = y0 - xz[j * 3 + 1];
        float dz = z0 - xz[j * 3 + 2];
        sd[j] = dx * dx + dy * dy + dz * dz
              + (1.0f - mm * mask[(long)t * M_ + j]) * 1e6f;
    }
    __syncthreads();

    for (int r = 0; r < K_ + 1; ++r) {
        float bv = INFINITY;
        int   bi = M_;
        for (int j = tid; j < M_; j += 128) {
            float d = sd[j];
            if (d < bv || (d == bv && j < bi)) { bv = d; bi = j; }
        }
        rv[tid] = bv; ri[tid] = bi;
        __syncthreads();
        for (int s = 64; s > 0; s >>= 1) {
            if (tid < s) {
                if (rv[tid + s] < rv[tid] ||
                    (rv[tid + s] == rv[tid] && ri[tid + s] < ri[tid])) {
                    rv[tid] = rv[tid + s]; ri[tid] = ri[tid + s];
                }
            }
            __syncthreads();
        }
        int win = ri[0];
        if (tid == 0) {
            if (r > 0) knn[(long)blockIdx.x * K_ + (r - 1)] = win;
            sd[win] = INFINITY;
        }
        __syncthreads();
    }
}

// ---------------------------------------------------------------------------
// out[t,d,m] = cfc2[t,m,d] + features[t,d,m]
// ---------------------------------------------------------------------------
__global__ void out_kernel(const float* __restrict__ cfc2,
                           const float* __restrict__ features,
                           float* __restrict__ out)
{
    const long i = (long)blockIdx.x * blockDim.x + threadIdx.x;
    if (i >= (long)T_ * D_ * M_) return;
    const int  m  = (int)(i & 4095);
    const long td = i >> 12;
    const int  d  = (int)(td & 127);
    const int  t  = (int)(td >> 7);
    out[i] = cfc2[((long)t * M_ + m) * 128 + d] + features[i];
}

// ---------------------------------------------------------------------------
// Launch
// ---------------------------------------------------------------------------
extern "C" void kernel_launch(void* const* d_in, const int* in_sizes, int n_in,
                              void* d_out, int out_size)
{
    const float* features = (const float*)d_in[0];
    const float* xyz      = (const float*)d_in[1];
    const float* mask     = (const float*)d_in[2];
    const float* fc1_w    = (const float*)d_in[3];
    const float* fc1_b    = (const float*)d_in[4];
    const float* fc2_w    = (const float*)d_in[5];
    const float* fc2_b    = (const float*)d_in[6];
    const float* dw1      = (const float*)d_in[7];
    const float* db1      = (const float*)d_in[8];
    const float* dw2      = (const float*)d_in[9];
    const float* db2      = (const float*)d_in[10];
    const float* gw1      = (const float*)d_in[11];
    const float* gb1      = (const float*)d_in[12];
    const float* gw2      = (const float*)d_in[13];
    const float* gb2      = (const float*)d_in[14];
    const float* wq       = (const float*)d_in[15];
    const float* wk       = (const float*)d_in[16];
    const float* wv       = (const float*)d_in[17];
    float* out = (float*)d_out;

    const int GEMM_SMEM  = 2048 + 2 * TILEB;               // 71680
    const int FUSED_SMEM = 2048 + 4 * TILEB + 32768;       // 174080
    const int XPROJ_SMEM = (128 * 64 + 128 * 128) * 4;     // 96KB

    cudaFuncSetAttribute((const void*)mma_gemm<ASRC_PLAIN>,
                         cudaFuncAttributeMaxDynamicSharedMemorySize, GEMM_SMEM);
    cudaFuncSetAttribute((const void*)mma_gemm<ASRC_POSH>,
                         cudaFuncAttributeMaxDynamicSharedMemorySize, GEMM_SMEM);
    cudaFuncSetAttribute((const void*)gamma_soft_mma,
                         cudaFuncAttributeMaxDynamicSharedMemorySize, FUSED_SMEM);
    cudaFuncSetAttribute((const void*)xproj_kernel,
                         cudaFuncAttributeMaxDynamicSharedMemorySize, XPROJ_SMEM);

    float *q, *k, *v, *pos, *zero;
    __nv_bfloat16 *xbf, *resb, *wimg;
    int* knn;
    cudaGetSymbolAddress((void**)&xbf,  g_xbf);
    cudaGetSymbolAddress((void**)&q,    g_q);
    cudaGetSymbolAddress((void**)&k,    g_k);
    cudaGetSymbolAddress((void**)&v,    g_v);
    cudaGetSymbolAddress((void**)&pos,  g_pos);
    cudaGetSymbolAddress((void**)&resb, g_resb);
    cudaGetSymbolAddress((void**)&knn,  g_knn);
    cudaGetSymbolAddress((void**)&zero, g_zero);
    cudaGetSymbolAddress((void**)&wimg, g_wimg);
    float* fc2o = q;   // q is dead after the fused kernel

    // 0) bf16 W^T images: 0=wq 1=wk 2=wv 3=dw2 4=gw1 5=gw2 6=fc2
    {
        WP wp; wp.w[0] = wq; wp.w[1] = wk; wp.w[2] = wv; wp.w[3] = dw2;
        wp.w[4] = gw1; wp.w[5] = gw2; wp.w[6] = fc2_w;
        prep_weights<<<7, 256>>>(wp, wimg);
    }

    // 1) x = feats @ fc1_w + fc1_b (bf16 out)
    {
        dim3 grid(M_ / 64, T_);
        xproj_kernel<<<grid, 256, XPROJ_SMEM>>>(features, fc1_w, fc1_b, xbf);
    }

    // 2) KNN
    knn_kernel<<<RP, 128>>>(xyz, mask, knn);

    // 3) q, k, v  (tensor core; zero bias)
    {
        MG p{}; p.Abf = xbf; p.bias = zero;
        p.Bimg = wimg;                 p.C = q;
        mma_gemm<ASRC_PLAIN><<<RP / 128, 256, GEMM_SMEM>>>(p);
        p.Bimg = wimg + 16384;         p.C = k;
        mma_gemm<ASRC_PLAIN><<<RP / 128, 256, GEMM_SMEM>>>(p);
        p.Bimg = wimg + 2 * 16384;     p.C = v;
        mma_gemm<ASRC_PLAIN><<<RP / 128, 256, GEMM_SMEM>>>(p);
    }

    // 4) pos = relu(rel @ dw1 + db1) @ dw2 + db2
    {
        MG p{}; p.Bimg = wimg + 3 * 16384; p.bias = db2; p.C = pos;
        p.xyz = xyz; p.knn = knn; p.w1 = dw1; p.b1 = db1;
        mma_gemm<ASRC_POSH><<<RN / 128, 256, GEMM_SMEM>>>(p);
    }

    // 5) fused gamma MLP + softmax + aggregate -> res (bf16)
    {
        GF p{};
        p.q = q; p.k = k; p.v = v; p.pos = pos; p.knn = knn;
        p.B1img = wimg + 4 * 16384; p.B2img = wimg + 5 * 16384;
        p.b1 = gb1; p.b2 = gb2; p.res = resb;
        gamma_soft_mma<<<RN / 128, 256, FUSED_SMEM>>>(p);
    }

    // 6) fc2 + residual + transpose
    {
        MG p{}; p.Abf = resb; p.Bimg = wimg + 6 * 16384; p.bias = fc2_b; p.C = fc2o;
        mma_gemm<ASRC_PLAIN><<<RP / 128, 256, GEMM_SMEM>>>(p);
    }
    {
        long total = (long)T_ * D_ * M_;
        int blocks = (int)((total + 255) / 256);
        out_kernel<<<blocks, 256>>>(fc2o, features, out);
    }
    (void)in_sizes; (void)n_in; (void)out_size;
}

// round 12
// speedup vs baseline: 2.5772x; 1.2689x over previous
#include <cuda_runtime.h>
#include <cuda_bf16.h>
#include <math.h>
#include <stdint.h>

// ---------------------------------------------------------------------------
// Problem constants
// ---------------------------------------------------------------------------
namespace {
constexpr int T_  = 4;
constexpr int N_  = 512;
constexpr int C_  = 8;
constexpr int D_  = 128;
constexpr int DM_ = 128;
constexpr int K_  = 16;
constexpr int M_  = N_ * C_;     // 4096
constexpr int RP  = T_ * M_;     // 16384
constexpr int RN  = RP * K_;     // 262144

constexpr int PK    = 136;             // padded bf16 row stride (272 B)
constexpr int TILEB = 128 * PK * 2;    // 34816 bytes per 128x128 bf16 tile
constexpr int PAW   = 132;             // padded fp32 stride for the 'a' tile
}

extern __shared__ __align__(1024) char dsm[];

// ---------------------------------------------------------------------------
// Scratch (device globals; zero-initialized; no allocation allowed)
// ---------------------------------------------------------------------------
__device__ float          g_zero[128];
__device__ __nv_bfloat16  g_xbf [RP * DM_];
__device__ float          g_q   [RP * DM_];
__device__ float          g_k   [RP * DM_];
__device__ float          g_v   [RP * DM_];
__device__ float          g_pos [RN * DM_];
__device__ __nv_bfloat16  g_resb[RP * DM_];
__device__ int            g_knn [RP * K_];
__device__ __nv_bfloat16  g_wimg[7 * 16384];   // bf16 W^T images, [n][k] row-major

// ---------------------------------------------------------------------------
// Warp-level bf16 MMA (baseline PTX, supported on plain sm_103 target)
// ---------------------------------------------------------------------------
__device__ __forceinline__ void mma16816(float* c, const uint32_t* a,
                                         uint32_t b0, uint32_t b1) {
    asm volatile(
        "mma.sync.aligned.m16n8k16.row.col.f32.bf16.bf16.f32 "
        "{%0,%1,%2,%3}, {%4,%5,%6,%7}, {%8,%9}, {%0,%1,%2,%3};"
        : "+f"(c[0]), "+f"(c[1]), "+f"(c[2]), "+f"(c[3])
        : "r"(a[0]), "r"(a[1]), "r"(a[2]), "r"(a[3]), "r"(b0), "r"(b1));
}

// Warp computes a 32x64 slice of C = A[128xK=128] @ B^T (B stored [n][k]).
// PK=136 padding: bank = (row*68 + word) & 31 -> conflict-free fragments.
__device__ __forceinline__ void warp_mma_tile(
    const __nv_bfloat16* sA, const __nv_bfloat16* sB,
    int wm, int wn, int lane, float acc[2][8][4])
{
    const int rq = lane >> 2;
    const int qc = (lane & 3) * 2;
#pragma unroll
    for (int ks = 0; ks < 8; ++ks) {
        const int k0 = ks * 16;
        uint32_t a[2][4];
#pragma unroll
        for (int mt = 0; mt < 2; ++mt) {
            const __nv_bfloat16* ar = sA + (wm * 32 + mt * 16 + rq) * PK + k0 + qc;
            a[mt][0] = *(const uint32_t*)(ar);
            a[mt][1] = *(const uint32_t*)(ar + 8 * PK);
            a[mt][2] = *(const uint32_t*)(ar + 8);
            a[mt][3] = *(const uint32_t*)(ar + 8 * PK + 8);
        }
#pragma unroll
        for (int nt = 0; nt < 8; ++nt) {
            const __nv_bfloat16* br = sB + (wn * 64 + nt * 8 + rq) * PK + k0 + qc;
            uint32_t b0 = *(const uint32_t*)(br);
            uint32_t b1 = *(const uint32_t*)(br + 8);
            mma16816(acc[0][nt], a[0], b0, b1);
            mma16816(acc[1][nt], a[1], b0, b1);
        }
    }
}

// ---------------------------------------------------------------------------
// Weight prep: img[b][n][k] = bf16(W_b[k][n])
// ---------------------------------------------------------------------------
struct WP { const float* w[7]; };
__global__ void prep_weights(WP p, __nv_bfloat16* img)
{
    const int b = blockIdx.x;
    const float* W = p.w[b];
    __nv_bfloat16* base = img + b * 16384;
    for (int i = threadIdx.x; i < 16384; i += blockDim.x) {
        int n = i >> 7, k = i & 127;
        base[i] = __float2bfloat16(W[k * 128 + n]);
    }
}

// ---------------------------------------------------------------------------
// Tensor-core GEMM: C[128-row tile][128] = A @ W + bias (fp32 out).
// blockIdx.y selects (Bimg, C) pair -> q/k/v in ONE launch.
// 256 threads; smem 2048 + 2*TILEB = 71680 -> 2 CTA/SM.
// ---------------------------------------------------------------------------
enum { ASRC_PLAIN = 0, ASRC_POSH = 1 };
struct MG {
    const __nv_bfloat16* Abf;
    const __nv_bfloat16* Bimg[3];
    float* C[3];
    const float* bias;
    const float* xyz; const int* knn; const float* w1; const float* b1;
};

template <int ASRC>
__global__ void __launch_bounds__(256, 2) mma_gemm(MG p)
{
    char* smem = dsm;
    float* sbias = (float*)smem;                       // 512 B
    float* srel  = (float*)(smem + 512);               // 1536 B (POSH)
    __nv_bfloat16* sA = (__nv_bfloat16*)(smem + 2048);
    __nv_bfloat16* sB = (__nv_bfloat16*)(smem + 2048 + TILEB);

    const int tid = threadIdx.x;
    const long bm = (long)blockIdx.x * 128;
    const __nv_bfloat16* Bimg = p.Bimg[blockIdx.y];
    float* Cout = p.C[blockIdx.y];

    if (tid < 128) sbias[tid] = p.bias[tid];

    for (int i = tid * 8; i < 128 * 128; i += 256 * 8) {
        int n = i >> 7, c8 = i & 127;
        *(uint4*)&sB[n * PK + c8] = *(const uint4*)&Bimg[i];
    }

    if (ASRC == ASRC_POSH) {
        if (tid < 128) {
            long gr = bm + tid;
            int idx = p.knn[gr];
            int tm  = (int)(gr >> 4);
            int t   = tm >> 12;
            int m   = tm & 4095;
            const float* xz = p.xyz + (long)t * M_ * 3;
            srel[tid * 3 + 0] = xz[m * 3 + 0] - xz[idx * 3 + 0];
            srel[tid * 3 + 1] = xz[m * 3 + 1] - xz[idx * 3 + 1];
            srel[tid * 3 + 2] = xz[m * 3 + 2] - xz[idx * 3 + 2];
        }
        __syncthreads();
        for (int it = 0; it < 8; ++it) {
            int el  = it * 256 + tid;
            int row = el >> 4;
            int c8  = (el & 15) * 8;
            float rx = srel[row * 3 + 0];
            float ry = srel[row * 3 + 1];
            float rz = srel[row * 3 + 2];
            __nv_bfloat16 buf[8];
#pragma unroll
            for (int j = 0; j < 8; ++j) {
                int c = c8 + j;
                float v = fmaf(rx, p.w1[c], fmaf(ry, p.w1[128 + c],
                            fmaf(rz, p.w1[256 + c], p.b1[c])));
                buf[j] = __float2bfloat16(fmaxf(v, 0.f));
            }
            *(uint4*)&sA[row * PK + c8] = *(uint4*)buf;
        }
    } else {
        for (int it = 0; it < 8; ++it) {
            int el  = it * 256 + tid;
            int row = el >> 4;
            int c8  = (el & 15) * 8;
            *(uint4*)&sA[row * PK + c8] = *(const uint4*)&p.Abf[(bm + row) * 128 + c8];
        }
    }
    __syncthreads();

    const int lane = tid & 31;
    const int wm = tid >> 6;
    const int wn = (tid >> 5) & 1;
    float acc[2][8][4];
#pragma unroll
    for (int mt = 0; mt < 2; ++mt)
#pragma unroll
        for (int nt = 0; nt < 8; ++nt)
#pragma unroll
            for (int c = 0; c < 4; ++c) acc[mt][nt][c] = 0.f;

    warp_mma_tile(sA, sB, wm, wn, lane, acc);

    const int rq = lane >> 2;
    const int qc = (lane & 3) * 2;
#pragma unroll
    for (int mt = 0; mt < 2; ++mt) {
#pragma unroll
        for (int nt = 0; nt < 8; ++nt) {
            int R  = wm * 32 + mt * 16 + rq;
            int Cc = wn * 64 + nt * 8 + qc;
            float bx = sbias[Cc], by = sbias[Cc + 1];
            float2 lo = make_float2(acc[mt][nt][0] + bx, acc[mt][nt][1] + by);
            float2 hi = make_float2(acc[mt][nt][2] + bx, acc[mt][nt][3] + by);
            *(float2*)&Cout[(bm + R) * 128 + Cc]     = lo;
            *(float2*)&Cout[(bm + R + 8) * 128 + Cc] = hi;
        }
    }
}

// ---------------------------------------------------------------------------
// Fused gamma MLP + softmax + aggregate (mma.sync), 2 CTA/SM version.
// Regions: R1 @2048 = B1 -> H; R2 @2048+T = B2; R3 @2048+2T = A(a0).
// aW fp32 [128][132] overlays R2+R3 after MMA2. pos re-read from gmem.
// smem total = 2048 + 3*TILEB = 106496 -> 2 CTA/SM (16 warps).
// ---------------------------------------------------------------------------
struct GF {
    const float* q; const float* k; const float* v; const float* pos;
    const int* knn;
    const __nv_bfloat16* B1img; const __nv_bfloat16* B2img;
    const float* b1; const float* b2;
    __nv_bfloat16* res;
};

__global__ void __launch_bounds__(256, 2) gamma_soft_mma(GF p)
{
    char* smem = dsm;
    int*   sidx = (int*)smem;                          // 512 B
    float* sb1v = (float*)(smem + 512);                // 512 B
    float* sb2v = (float*)(smem + 1024);               // 512 B
    __nv_bfloat16* sB1 = (__nv_bfloat16*)(smem + 2048);            // R1 (-> H)
    __nv_bfloat16* sB2 = (__nv_bfloat16*)(smem + 2048 + TILEB);    // R2
    __nv_bfloat16* sA  = (__nv_bfloat16*)(smem + 2048 + 2 * TILEB);// R3
    __nv_bfloat16* sH  = sB1;                                       // reuse R1
    float* aW = (float*)(smem + 2048 + TILEB);         // overlays R2+R3 (67584B)

    const int tid = threadIdx.x;
    const long bm = (long)blockIdx.x * 128;    // neighbor-row base
    const int tp0 = blockIdx.x * 8;            // first point
    const int t   = tp0 >> 12;

    if (tid < 128) {
        sidx[tid] = p.knn[bm + tid];
        sb1v[tid] = p.b1[tid];
        sb2v[tid] = p.b2[tid];
    }
    for (int i = tid * 8; i < 128 * 128; i += 256 * 8) {
        int n = i >> 7, c8 = i & 127;
        *(uint4*)&sB1[n * PK + c8] = *(const uint4*)&p.B1img[i];
        *(uint4*)&sB2[n * PK + c8] = *(const uint4*)&p.B2img[i];
    }
    __syncthreads();

    // build a0 tile (padded bf16)
    for (int it = 0; it < 8; ++it) {
        int el  = it * 256 + tid;
        int row = el >> 4;
        int c8  = (el & 15) * 8;
        int tm  = tp0 + (row >> 4);
        const float* qp = &p.q[(long)tm * 128 + c8];
        const float* kp = &p.k[(((long)t << 12) + sidx[row]) * 128 + c8];
        const float* pp = &p.pos[(bm + row) * 128 + c8];
        __nv_bfloat16 abuf[8];
#pragma unroll
        for (int j = 0; j < 8; ++j)
            abuf[j] = __float2bfloat16(qp[j] - kp[j] + pp[j]);
        *(uint4*)&sA[row * PK + c8] = *(uint4*)abuf;
    }
    __syncthreads();

    const int lane = tid & 31;
    const int wm = tid >> 6;
    const int wn = (tid >> 5) & 1;
    const int rq = lane >> 2;
    const int qc = (lane & 3) * 2;

    // MMA1: a0 @ B1
    float acc[2][8][4];
#pragma unroll
    for (int mt = 0; mt < 2; ++mt)
#pragma unroll
        for (int nt = 0; nt < 8; ++nt)
#pragma unroll
            for (int c = 0; c < 4; ++c) acc[mt][nt][c] = 0.f;
    warp_mma_tile(sA, sB1, wm, wn, lane, acc);
    __syncthreads();   // all warps done reading B1 before H overwrites it

    // h = relu(acc + b1) -> bf16 padded into R1 (was B1)
#pragma unroll
    for (int mt = 0; mt < 2; ++mt) {
#pragma unroll
        for (int nt = 0; nt < 8; ++nt) {
            int R  = wm * 32 + mt * 16 + rq;
            int Cc = wn * 64 + nt * 8 + qc;
            float bx = sb1v[Cc], by = sb1v[Cc + 1];
            __nv_bfloat16 h0[2], h1[2];
            h0[0] = __float2bfloat16(fmaxf(acc[mt][nt][0] + bx, 0.f));
            h0[1] = __float2bfloat16(fmaxf(acc[mt][nt][1] + by, 0.f));
            h1[0] = __float2bfloat16(fmaxf(acc[mt][nt][2] + bx, 0.f));
            h1[1] = __float2bfloat16(fmaxf(acc[mt][nt][3] + by, 0.f));
            *(uint32_t*)&sH[R * PK + Cc]       = *(uint32_t*)h0;
            *(uint32_t*)&sH[(R + 8) * PK + Cc] = *(uint32_t*)h1;
        }
    }
    __syncthreads();

    // MMA2: h @ B2
#pragma unroll
    for (int mt = 0; mt < 2; ++mt)
#pragma unroll
        for (int nt = 0; nt < 8; ++nt)
#pragma unroll
            for (int c = 0; c < 4; ++c) acc[mt][nt][c] = 0.f;
    warp_mma_tile(sH, sB2, wm, wn, lane, acc);
    __syncthreads();   // all warps done reading B2/A before aW overlay

    const float scale = 0.08838834764831845f;  // 1/sqrt(128)
#pragma unroll
    for (int mt = 0; mt < 2; ++mt) {
#pragma unroll
        for (int nt = 0; nt < 8; ++nt) {
            int R  = wm * 32 + mt * 16 + rq;
            int Cc = wn * 64 + nt * 8 + qc;
            float bx = sb2v[Cc], by = sb2v[Cc + 1];
            float2 lo = make_float2((acc[mt][nt][0] + bx) * scale,
                                    (acc[mt][nt][1] + by) * scale);
            float2 hi = make_float2((acc[mt][nt][2] + bx) * scale,
                                    (acc[mt][nt][3] + by) * scale);
            *(float2*)&aW[R * PAW + Cc]       = lo;
            *(float2*)&aW[(R + 8) * PAW + Cc] = hi;
        }
    }
    __syncthreads();

    // softmax over K + aggregate relu(v_gather + pos)  (pos from gmem)
    for (int rep = 0; rep < 4; ++rep) {
        const int pp = rep * 2 + (tid >> 7);   // point 0..7
        const int c  = tid & 127;
        const int r0 = pp * 16;

        float av[K_];
        float mx = -INFINITY;
#pragma unroll
        for (int kk = 0; kk < K_; ++kk) {
            av[kk] = aW[(r0 + kk) * PAW + c];
            mx = fmaxf(mx, av[kk]);
        }
        float s = 0.f;
#pragma unroll
        for (int kk = 0; kk < K_; ++kk) {
            av[kk] = __expf(av[kk] - mx);
            s += av[kk];
        }
        const float inv = 1.f / s;

        float r = 0.f;
#pragma unroll
        for (int kk = 0; kk < K_; ++kk) {
            float vv = p.v[(((long)t << 12) + sidx[r0 + kk]) * 128 + c]
                     + p.pos[(bm + r0 + kk) * 128 + c];
            r = fmaf(av[kk], fmaxf(vv, 0.f), r);
        }
        p.res[(long)(tp0 + pp) * 128 + c] = __float2bfloat16(r * inv);
    }
}

// ---------------------------------------------------------------------------
// x = feats @ fc1_w + fc1_b (transpose of features fused), output bf16.
// ---------------------------------------------------------------------------
__global__ void xproj_kernel(const float* __restrict__ features,
                             const float* __restrict__ W,
                             const float* __restrict__ bias,
                             __nv_bfloat16* __restrict__ X)
{
    float* smf = (float*)dsm;
    float* sAT = smf;                 // [128 d][64 ml]
    float* sB  = smf + 128 * 64;      // [128][128]

    const int tid = threadIdx.x;
    const int t   = blockIdx.y;
    const int bm  = blockIdx.x * 64;

    for (int i = tid * 4; i < 128 * 128; i += 1024)
        *(float4*)&sB[i] = *(const float4*)&W[i];
    for (int i = tid; i < 128 * 64; i += 256) {
        int d  = i >> 6;
        int ml = i & 63;
        sAT[d * 64 + ml] = features[((long)t * D_ + d) * M_ + bm + ml];
    }
    __syncthreads();

    const int cg = tid & 31;
    const int rg = tid >> 5;
    float acc[8][4];
#pragma unroll
    for (int j = 0; j < 8; ++j)
#pragma unroll
        for (int c = 0; c < 4; ++c) acc[j][c] = 0.f;

#pragma unroll 8
    for (int d = 0; d < 128; ++d) {
        float4 b = *(float4*)&sB[d * 128 + cg * 4];
#pragma unroll
        for (int j = 0; j < 8; ++j) {
            float a = sAT[d * 64 + rg * 8 + j];
            acc[j][0] = fmaf(a, b.x, acc[j][0]);
            acc[j][1] = fmaf(a, b.y, acc[j][1]);
            acc[j][2] = fmaf(a, b.z, acc[j][2]);
            acc[j][3] = fmaf(a, b.w, acc[j][3]);
        }
    }

    float4 bb = *(const float4*)&bias[cg * 4];
#pragma unroll
    for (int j = 0; j < 8; ++j) {
        __nv_bfloat16 ob[4];
        ob[0] = __float2bfloat16(acc[j][0] + bb.x);
        ob[1] = __float2bfloat16(acc[j][1] + bb.y);
        ob[2] = __float2bfloat16(acc[j][2] + bb.z);
        ob[3] = __float2bfloat16(acc[j][3] + bb.w);
        *(uint2*)&X[((long)t * M_ + bm + rg * 8 + j) * 128 + cg * 4] = *(uint2*)ob;
    }
}

// ---------------------------------------------------------------------------
// KNN v2: distances in per-thread registers; shfl-based block argmin;
// only the winner's owner thread rescans its 32-element stripe.
// Stable (d, j) lexicographic selection == jnp.argsort stable order.
// ---------------------------------------------------------------------------
__global__ void __launch_bounds__(128) knn_kernel(
    const float* __restrict__ xyz,
    const float* __restrict__ mask,
    int* __restrict__ knn)
{
    __shared__ float swv[4];
    __shared__ int   swi[4];
    __shared__ int   sgidx;

    const int t = blockIdx.x >> 12;
    const int m = blockIdx.x & 4095;
    const int tid = threadIdx.x;
    const int lane = tid & 31;
    const int warp = tid >> 5;

    const float* xz = xyz + (long)t * M_ * 3;
    const float x0 = xz[m * 3 + 0];
    const float y0 = xz[m * 3 + 1];
    const float z0 = xz[m * 3 + 2];
    const float mm = mask[(long)t * M_ + m];

    float dl[32];
    float bv = INFINITY;
    int   bi = M_;
#pragma unroll
    for (int ii = 0; ii < 32; ++ii) {
        int j = tid + ii * 128;
        float dx = x0 - xz[j * 3 + 0];
        float dy = y0 - xz[j * 3 + 1];
        float dz = z0 - xz[j * 3 + 2];
        float d  = dx * dx + dy * dy + dz * dz
                 + (1.0f - mm * mask[(long)t * M_ + j]) * 1e6f;
        dl[ii] = d;
        if (d < bv || (d == bv && j < bi)) { bv = d; bi = j; }
    }

    for (int r = 0; r < K_ + 1; ++r) {
        // warp argmin via shfl (stable by index)
        float v = bv; int i = bi;
#pragma unroll
        for (int s = 16; s > 0; s >>= 1) {
            float ov = __shfl_down_sync(0xffffffffu, v, s);
            int   oi = __shfl_down_sync(0xffffffffu, i, s);
            if (ov < v || (ov == v && oi < i)) { v = ov; i = oi; }
        }
        if (lane == 0) { swv[warp] = v; swi[warp] = i; }
        __syncthreads();
        if (tid == 0) {
            float gv = swv[0]; int gi = swi[0];
#pragma unroll
            for (int w = 1; w < 4; ++w) {
                if (swv[w] < gv || (swv[w] == gv && swi[w] < gi)) {
                    gv = swv[w]; gi = swi[w];
                }
            }
            sgidx = gi;
            if (r > 0) knn[(long)blockIdx.x * K_ + (r - 1)] = gi;
        }
        __syncthreads();
        const int win = sgidx;
        if ((win & 127) == tid) {           // owner removes winner + rescans
            const int kill = win >> 7;
#pragma unroll
            for (int ii = 0; ii < 32; ++ii)
                if (ii == kill) dl[ii] = INFINITY;
            bv = INFINITY; bi = M_;
#pragma unroll
            for (int ii = 0; ii < 32; ++ii) {
                int j = tid + ii * 128;
                float d = dl[ii];
                if (d < bv || (d == bv && j < bi)) { bv = d; bi = j; }
            }
        }
        __syncthreads();   // WAR on swv/swi + sgidx before next round
    }
}

// ---------------------------------------------------------------------------
// out[t,d,m] = cfc2[t,m,d] + features[t,d,m]
// ---------------------------------------------------------------------------
__global__ void out_kernel(const float* __restrict__ cfc2,
                           const float* __restrict__ features,
                           float* __restrict__ out)
{
    const long i = (long)blockIdx.x * blockDim.x + threadIdx.x;
    if (i >= (long)T_ * D_ * M_) return;
    const int  m  = (int)(i & 4095);
    const long td = i >> 12;
    const int  d  = (int)(td & 127);
    const int  t  = (int)(td >> 7);
    out[i] = cfc2[((long)t * M_ + m) * 128 + d] + features[i];
}

// ---------------------------------------------------------------------------
// Launch
// ---------------------------------------------------------------------------
extern "C" void kernel_launch(void* const* d_in, const int* in_sizes, int n_in,
                              void* d_out, int out_size)
{
    const float* features = (const float*)d_in[0];
    const float* xyz      = (const float*)d_in[1];
    const float* mask     = (const float*)d_in[2];
    const float* fc1_w    = (const float*)d_in[3];
    const float* fc1_b    = (const float*)d_in[4];
    const float* fc2_w    = (const float*)d_in[5];
    const float* fc2_b    = (const float*)d_in[6];
    const float* dw1      = (const float*)d_in[7];
    const float* db1      = (const float*)d_in[8];
    const float* dw2      = (const float*)d_in[9];
    const float* db2      = (const float*)d_in[10];
    const float* gw1      = (const float*)d_in[11];
    const float* gb1      = (const float*)d_in[12];
    const float* gw2      = (const float*)d_in[13];
    const float* gb2      = (const float*)d_in[14];
    const float* wq       = (const float*)d_in[15];
    const float* wk       = (const float*)d_in[16];
    const float* wv       = (const float*)d_in[17];
    float* out = (float*)d_out;

    const int GEMM_SMEM  = 2048 + 2 * TILEB;               // 71680
    const int FUSED_SMEM = 2048 + 3 * TILEB;               // 106496
    const int XPROJ_SMEM = (128 * 64 + 128 * 128) * 4;     // 96KB

    cudaFuncSetAttribute((const void*)mma_gemm<ASRC_PLAIN>,
                         cudaFuncAttributeMaxDynamicSharedMemorySize, GEMM_SMEM);
    cudaFuncSetAttribute((const void*)mma_gemm<ASRC_POSH>,
                         cudaFuncAttributeMaxDynamicSharedMemorySize, GEMM_SMEM);
    cudaFuncSetAttribute((const void*)gamma_soft_mma,
                         cudaFuncAttributeMaxDynamicSharedMemorySize, FUSED_SMEM);
    cudaFuncSetAttribute((const void*)xproj_kernel,
                         cudaFuncAttributeMaxDynamicSharedMemorySize, XPROJ_SMEM);

    float *q, *k, *v, *pos, *zero;
    __nv_bfloat16 *xbf, *resb, *wimg;
    int* knn;
    cudaGetSymbolAddress((void**)&xbf,  g_xbf);
    cudaGetSymbolAddress((void**)&q,    g_q);
    cudaGetSymbolAddress((void**)&k,    g_k);
    cudaGetSymbolAddress((void**)&v,    g_v);
    cudaGetSymbolAddress((void**)&pos,  g_pos);
    cudaGetSymbolAddress((void**)&resb, g_resb);
    cudaGetSymbolAddress((void**)&knn,  g_knn);
    cudaGetSymbolAddress((void**)&zero, g_zero);
    cudaGetSymbolAddress((void**)&wimg, g_wimg);
    float* fc2o = q;   // q is dead after the fused kernel

    // 0) bf16 W^T images: 0=wq 1=wk 2=wv 3=dw2 4=gw1 5=gw2 6=fc2
    {
        WP wp; wp.w[0] = wq; wp.w[1] = wk; wp.w[2] = wv; wp.w[3] = dw2;
        wp.w[4] = gw1; wp.w[5] = gw2; wp.w[6] = fc2_w;
        prep_weights<<<7, 256>>>(wp, wimg);
    }

    // 1) x = feats @ fc1_w + fc1_b (bf16 out)
    {
        dim3 grid(M_ / 64, T_);
        xproj_kernel<<<grid, 256, XPROJ_SMEM>>>(features, fc1_w, fc1_b, xbf);
    }

    // 2) KNN
    knn_kernel<<<RP, 128>>>(xyz, mask, knn);

    // 3) q, k, v in ONE launch (zero bias)
    {
        MG p{}; p.Abf = xbf; p.bias = zero;
        p.Bimg[0] = wimg;             p.C[0] = q;
        p.Bimg[1] = wimg + 16384;     p.C[1] = k;
        p.Bimg[2] = wimg + 2 * 16384; p.C[2] = v;
        dim3 grid(RP / 128, 3);
        mma_gemm<ASRC_PLAIN><<<grid, 256, GEMM_SMEM>>>(p);
    }

    // 4) pos = relu(rel @ dw1 + db1) @ dw2 + db2
    {
        MG p{}; p.Bimg[0] = wimg + 3 * 16384; p.bias = db2; p.C[0] = pos;
        p.xyz = xyz; p.knn = knn; p.w1 = dw1; p.b1 = db1;
        mma_gemm<ASRC_POSH><<<dim3(RN / 128, 1), 256, GEMM_SMEM>>>(p);
    }

    // 5) fused gamma MLP + softmax + aggregate -> res (bf16)
    {
        GF p{};
        p.q = q; p.k = k; p.v = v; p.pos = pos; p.knn = knn;
        p.B1img = wimg + 4 * 16384; p.B2img = wimg + 5 * 16384;
        p.b1 = gb1; p.b2 = gb2; p.res = resb;
        gamma_soft_mma<<<RN / 128, 256, FUSED_SMEM>>>(p);
    }

    // 6) fc2 + residual + transpose
    {
        MG p{}; p.Abf = resb; p.Bimg[0] = wimg + 6 * 16384;
        p.bias = fc2_b; p.C[0] = fc2o;
        mma_gemm<ASRC_PLAIN><<<dim3(RP / 128, 1), 256, GEMM_SMEM>>>(p);
    }
    {
        long total = (long)T_ * D_ * M_;
        int blocks = (int)((total + 255) / 256);
        out_kernel<<<blocks, 256>>>(fc2o, features, out);
    }
    (void)in_sizes; (void)n_in; (void)out_size;
}